// round 15
// baseline (speedup 1.0000x reference)
#include <cuda_runtime.h>

// Not-a-knot cubic spline upsample, 512 x 8192 fp32 -> 512 x 32768 fp32.
// [1,4,1] tridiagonal inverse = exponential Green's function (lam = sqrt(3)-2)
// composed with the 6*[1,-2,1] rhs into a 17-tap FIR on y -> M is LOCAL.
//
// step = 8191/32767: point m of chunk cg lies in interval cg-1 iff
// 8191*m < 3*cg (exact integer predicate) -> static warp-uniform A/B patterns,
// no floor/clamp/selects. Eval: scalar LDS + in-register coefficient build
// (the build arithmetic doubles as latency hiding for the LDS); per chunk
// 1 FMA + 1 SUB index math, per point 1 ADD + 3 FMA.
// This round: occupancy ceiling 6 -> 7 CTAs/SM (56 warps, 87.5%).

#define W_DIM  8192
#define NTHR   256
#define TILE_I 1024
#define KT     8
#define SYN    1056

#define LAM   (-0.26794919243112270647f)   // sqrt(3) - 2
#define ACOEF (0.28867513459481288225f)    // 1 / (2*sqrt(3))

__global__ __launch_bounds__(NTHR, 7)
void spline_kernel(const float* __restrict__ x, float* __restrict__ out,
                   int nout, float step) {
    __shared__ __align__(16) float syA[SYN + 8];   // 4-float zeroed front pad
    __shared__ __align__(16) float smA[SYN + 8];
    float* sy = syA + 4;
    float* sM = smA + 4;

    const int tid = threadIdx.x;
    const int n = W_DIM - 4;
    const int row = blockIdx.y;
    const int kbase = blockIdx.x * TILE_I;

    const float* xr = x + (size_t)row * W_DIM;
    float* outr = out + (size_t)row * nout + kbase * 4;

    const int ilo = (kbase >= 16) ? (kbase - 16) : 0;
    int ihi = kbase + TILE_I + 16; if (ihi > W_DIM) ihi = W_DIM;
    const int NY = ihi - ilo;

    // ---- load y slice (+halo), aligned float4; zero front pads ----
    {
        const float4* x4 = (const float4*)(xr + ilo);
        float4* sy4 = (float4*)sy;
        for (int v = tid; v < (NY >> 2); v += NTHR) sy4[v] = x4[v];
        if (tid < 4) { syA[tid] = 0.f; smA[tid] = 0.f; }
    }
    __syncthreads();

    // ---- interior M via 17-tap symmetric FIR on y -> sM ----
    {
        const float C0 = -4.3923048f;
        const float C[KT] = { 2.7846097f, -0.7461340f, 0.1999261f, -0.0535701f,
                              0.0143541f, -0.0038462f, 0.0010306f, -0.0002761f };
        const int FLO = (ilo == 0) ? 20 : 12;
        int ghi = kbase + TILE_I;
        if (ghi > W_DIM - 21) ghi = W_DIM - 21;
        const int nch = ((ghi - (ilo + FLO)) >> 2) + 1;
        for (int c = tid; c < nch; c += NTHR) {
            const int li0 = FLO + 4 * c;                // li0 % 4 == 0
            float win[20];                              // y[li0-8 .. li0+11]
            const float4* ws = (const float4*)(sy + li0 - 8);
            #pragma unroll
            for (int v = 0; v < 5; ++v) ((float4*)win)[v] = ws[v];
            #pragma unroll
            for (int m = 0; m < 4; ++m) {
                float acc = C0 * win[8 + m];
                #pragma unroll
                for (int k = 1; k <= KT; ++k)
                    acc = fmaf(C[k - 1], win[8 + m - k] + win[8 + m + k], acc);
                if (ilo + li0 + m <= ghi) sM[li0 + m] = acc;
            }
        }
    }

    // ---- left edge (row-start tile): exact M[0..19] via Green sums ----
    if (ilo == 0 && tid < 20) {
        const float M1 = sy[2] - 2.f * sy[1] + sy[0];
        float SL = 0.f, lp = LAM;
        #pragma unroll 4
        for (int j = 0; j < 24; ++j) {
            float b = 6.f * (sy[j + 3] - 2.f * sy[j + 2] + sy[j + 1]);
            if (j == 0) b -= M1;
            SL = fmaf(lp, b, SL);
            lp *= LAM;
        }
        float Mv;
        if (tid == 1) {
            Mv = M1;
        } else {
            const int jj = (tid == 0) ? 0 : tid - 2;
            float acc = 0.f, p = 1.f;
            #pragma unroll 4
            for (int d = 0; d <= 12; ++d) {
                const int j = jj - d;
                if (j >= 0) {
                    float b = 6.f * (sy[j + 3] - 2.f * sy[j + 2] + sy[j + 1]);
                    if (j == 0) b -= M1;
                    acc = fmaf(p, b, acc);
                }
                p *= LAM;
            }
            p = LAM;
            #pragma unroll 4
            for (int d = 1; d <= 12; ++d) {
                const int j = jj + d;                   // always < n
                float b = 6.f * (sy[j + 3] - 2.f * sy[j + 2] + sy[j + 1]);
                acc = fmaf(p, b, acc);
                p *= LAM;
            }
            float pw = LAM;                             // lam^{jj+1}
            for (int s = 0; s < jj; ++s) pw *= LAM;
            acc -= pw * SL;
            Mv = ACOEF * acc;
            if (tid == 0) Mv = 2.f * M1 - Mv;
        }
        sM[tid] = Mv;
    }

    // ---- right edge (row-end tile): exact M[W-20..W-1] ----
    if (kbase + TILE_I == W_DIM && tid >= 32 && tid < 52) {
        const int t = tid - 32;
        const int gi = W_DIM - 20 + t;
        const int lW = W_DIM - ilo;
        const float Mn2 = sy[lW - 1] - 2.f * sy[lW - 2] + sy[lW - 3];
        float SR = 0.f, lp = LAM;
        #pragma unroll 4
        for (int m = 0; m < 24; ++m) {
            const int j = n - 1 - m;
            float b = 6.f * (sy[j + 3 - ilo] - 2.f * sy[j + 2 - ilo] + sy[j + 1 - ilo]);
            if (j == n - 1) b -= Mn2;
            SR = fmaf(lp, b, SR);
            lp *= LAM;
        }
        float Mv;
        if (t == 18) {
            Mv = Mn2;                                   // gi == W-2
        } else {
            const int jj = (t == 19) ? (n - 1) : (gi - 2);
            float acc = 0.f, p = 1.f;
            #pragma unroll 4
            for (int d = 0; d <= 12; ++d) {
                const int j = jj - d;                   // always >= 0
                float b = 6.f * (sy[j + 3 - ilo] - 2.f * sy[j + 2 - ilo] + sy[j + 1 - ilo]);
                if (j == n - 1) b -= Mn2;
                acc = fmaf(p, b, acc);
                p *= LAM;
            }
            p = LAM;
            #pragma unroll 4
            for (int d = 1; d <= 12; ++d) {
                const int j = jj + d;
                if (j < n) {
                    float b = 6.f * (sy[j + 3 - ilo] - 2.f * sy[j + 2 - ilo] + sy[j + 1 - ilo]);
                    acc = fmaf(p, b, acc);
                }
                p *= LAM;
            }
            float pw = LAM;                             // lam^{n-jj}
            for (int s = 0; s < n - 1 - jj; ++s) pw *= LAM;
            acc -= pw * SR;
            Mv = ACOEF * acc;
            if (t == 19) Mv = 2.f * Mn2 - Mv;
        }
        sM[gi - ilo] = Mv;
    }
    __syncthreads();

    // ---- evaluate: static split; per chunk 1 FMA + 1 SUB index math,
    //      per point 1 ADD + 3 FMA ----
    {
        float4* out4 = (float4*)outr;
        const int loff = kbase - 1 - ilo;               // 15 interior, -1 first tile
        const float s1 = step;
        const float s2 = step + step;                   // exact
        const float s3 = 3.0f * step;                   // 1 rounding, ~1e-7 t jitter
        #pragma unroll
        for (int k = 0; k < TILE_I / NTHR; ++k) {
            const int cl = tid + k * NTHR;
            const int cg = kbase + cl;
            const int iL = cl + loff;
            const float q0f = (float)(4 * cg);          // exact
            const float fi0 = (float)(cg - 1);          // exact
            const float u0 = fmaf(q0f, step, -fi0);     // t of pt 0 on A, 0.5ulp
            const float ub0 = u0 - 1.0f;                // t of pt 0 on B, exact

            const float y0 = sy[iL], y1 = sy[iL + 1], y2 = sy[iL + 2];
            const float m0 = sM[iL], m1 = sM[iL + 1], m2 = sM[iL + 2];
            const float Ax = y0;
            const float Ay = fmaf(fmaf(2.f, m0, m1), -(1.f / 6.f), y1 - y0);
            const float Az = 0.5f * m0;
            const float Aw = (m1 - m0) * (1.f / 6.f);
            const float Bx = y1;
            const float By = fmaf(fmaf(2.f, m1, m2), -(1.f / 6.f), y2 - y1);
            const float Bz = 0.5f * m1;
            const float Bw = (m2 - m1) * (1.f / 6.f);

            #define EVA(t) fmaf((t), fmaf((t), fmaf((t), Aw, Az), Ay), Ax)
            #define EVB(t) fmaf((t), fmaf((t), fmaf((t), Bw, Bz), By), Bx)

            const int cg3 = 3 * cg;
            float4 r;
            if (cg3 > 16382) {                          // cg >= 5461
                if (cg == W_DIM - 1) {                  // cg == 8191: A A A A
                    r.x = EVA(u0);      r.y = EVA(u0 + s1);
                    r.z = EVA(u0 + s2); r.w = EVA(u0 + s3);
                } else {                                // A A A B
                    r.x = EVA(u0);      r.y = EVA(u0 + s1);
                    r.z = EVA(u0 + s2); r.w = EVB(ub0 + s3);
                }
            } else if (cg3 > 8191) {                    // cg in [2731,5460]: A A B B
                r.x = EVA(u0);       r.y = EVA(u0 + s1);
                r.z = EVB(ub0 + s2); r.w = EVB(ub0 + s3);
            } else if (cg3 > 0) {                       // cg in [1,2730]: A B B B
                r.x = EVA(u0);       r.y = EVB(ub0 + s1);
                r.z = EVB(ub0 + s2); r.w = EVB(ub0 + s3);
            } else {                                    // cg == 0 (fi0 = -1): B B B B
                r.x = EVB(ub0);      r.y = EVB(ub0 + s1);
                r.z = EVB(ub0 + s2); r.w = EVB(ub0 + s3);
            }
            #undef EVA
            #undef EVB
            out4[cl] = r;
        }
    }
}

extern "C" void kernel_launch(void* const* d_in, const int* in_sizes, int n_in,
                              void* d_out, int out_size) {
    const float* x = (const float*)d_in[0];
    float* out = (float*)d_out;

    const int B = in_sizes[0] / W_DIM;               // 512
    const int nout = out_size / B;                   // 32768
    const float step = (float)((double)(W_DIM - 1) / (double)(nout - 1));

    dim3 grid(W_DIM / TILE_I, B);                    // 8 x 512 = 4096 CTAs
    spline_kernel<<<grid, NTHR>>>(x, out, nout, step);
}

// round 16
// speedup vs baseline: 1.0026x; 1.0026x over previous
#include <cuda_runtime.h>

// Not-a-knot cubic spline upsample, 512 x 8192 fp32 -> 512 x 32768 fp32.
// [1,4,1] tridiagonal inverse = exponential Green's function (lam = sqrt(3)-2)
// composed with the 6*[1,-2,1] rhs into a 17-tap FIR on y -> M is LOCAL.
//
// ONE-BARRIER version: FIR reads y directly from global (overlapping windows,
// L1-served) and writes (y, M) float2 pairs into smem keyed by chunk slot
// (slot = knot - kbase + 1, so eval addressing is just cl). Eval per 4-output
// chunk: 3 LDS.64 + in-register coefficient build + static warp-uniform A/B
// interval patterns (8191*m < 3*cg exact integer predicate), per point
// 1 ADD + 3 FMA, coalesced STG.128.

#define W_DIM  8192
#define NTHR   256
#define TILE_I 1024
#define KT     8
#define SPN    1026      // knot slots 0..1025 = knots kbase-1 .. kbase+1024

#define LAM   (-0.26794919243112270647f)   // sqrt(3) - 2
#define ACOEF (0.28867513459481288225f)    // 1 / (2*sqrt(3))

__global__ __launch_bounds__(NTHR, 7)
void spline_kernel(const float* __restrict__ x, float* __restrict__ out,
                   int nout, float step) {
    __shared__ __align__(16) float2 sP[SPN];

    const int tid = threadIdx.x;
    const int n = W_DIM - 4;
    const int row = blockIdx.y;
    const int kbase = blockIdx.x * TILE_I;

    const float* xr = x + (size_t)row * W_DIM;
    float* outr = out + (size_t)row * nout + kbase * 4;

    const int ilo = (kbase >= 16) ? (kbase - 16) : 0;

    // ---- FIR (17-tap) on GLOBAL y -> (y, M) pairs in smem ----
    {
        const float C0 = -4.3923048f;
        const float C[KT] = { 2.7846097f, -0.7461340f, 0.1999261f, -0.0535701f,
                              0.0143541f, -0.0038462f, 0.0010306f, -0.0002761f };
        int gfirst = (kbase >= 1) ? (kbase - 1) : 20;   // first-tile edge owns 0..19
        int ghi = kbase + TILE_I;                       // knot kbase+1024 (slot 1025)
        if (ghi > W_DIM - 21) ghi = W_DIM - 21;         // last-tile edge owns the rest
        const int lstart = ((gfirst - ilo) >> 2) << 2;  // 4-aligned, >= 12
        const int nch = ((ghi - ilo - lstart) >> 2) + 1;
        for (int c = tid; c < nch; c += NTHR) {
            const int li0 = lstart + 4 * c;
            float win[20];                              // y[ilo+li0-8 .. +11]
            const float4* ws = (const float4*)(xr + ilo + li0 - 8);  // 16B aligned
            #pragma unroll
            for (int v = 0; v < 5; ++v) ((float4*)win)[v] = ws[v];
            #pragma unroll
            for (int m = 0; m < 4; ++m) {
                float acc = C0 * win[8 + m];
                #pragma unroll
                for (int k = 1; k <= KT; ++k)
                    acc = fmaf(C[k - 1], win[8 + m - k] + win[8 + m + k], acc);
                const int gi = ilo + li0 + m;
                if (gi >= gfirst && gi <= ghi)
                    sP[gi - kbase + 1] = make_float2(win[8 + m], acc);
            }
        }
    }

    // ---- left edge (row-start tile): knots 0..19 via Green sums (global y) ----
    if (kbase == 0 && tid < 20) {
        const float M1 = xr[2] - 2.f * xr[1] + xr[0];
        float SL = 0.f, lp = LAM;
        #pragma unroll 4
        for (int j = 0; j < 24; ++j) {
            float b = 6.f * (xr[j + 3] - 2.f * xr[j + 2] + xr[j + 1]);
            if (j == 0) b -= M1;
            SL = fmaf(lp, b, SL);
            lp *= LAM;
        }
        float Mv;
        if (tid == 1) {
            Mv = M1;
        } else {
            const int jj = (tid == 0) ? 0 : tid - 2;
            float acc = 0.f, p = 1.f;
            #pragma unroll 4
            for (int d = 0; d <= 12; ++d) {
                const int j = jj - d;
                if (j >= 0) {
                    float b = 6.f * (xr[j + 3] - 2.f * xr[j + 2] + xr[j + 1]);
                    if (j == 0) b -= M1;
                    acc = fmaf(p, b, acc);
                }
                p *= LAM;
            }
            p = LAM;
            #pragma unroll 4
            for (int d = 1; d <= 12; ++d) {
                const int j = jj + d;                   // always < n
                float b = 6.f * (xr[j + 3] - 2.f * xr[j + 2] + xr[j + 1]);
                acc = fmaf(p, b, acc);
                p *= LAM;
            }
            float pw = LAM;                             // lam^{jj+1}
            for (int s = 0; s < jj; ++s) pw *= LAM;
            acc -= pw * SL;
            Mv = ACOEF * acc;
            if (tid == 0) Mv = 2.f * M1 - Mv;
        }
        sP[tid + 1] = make_float2(xr[tid], Mv);         // knot tid
    }
    if (kbase == 0 && tid == 31) sP[0] = make_float2(0.f, 0.f);   // ghost knot -1

    // ---- right edge (row-end tile): knots W-20..W-1 (global y) ----
    if (kbase + TILE_I == W_DIM && tid >= 32 && tid < 52) {
        const int t = tid - 32;
        const int gi = W_DIM - 20 + t;
        const float Mn2 = xr[W_DIM - 1] - 2.f * xr[W_DIM - 2] + xr[W_DIM - 3];
        float SR = 0.f, lp = LAM;
        #pragma unroll 4
        for (int m = 0; m < 24; ++m) {
            const int j = n - 1 - m;
            float b = 6.f * (xr[j + 3] - 2.f * xr[j + 2] + xr[j + 1]);
            if (j == n - 1) b -= Mn2;
            SR = fmaf(lp, b, SR);
            lp *= LAM;
        }
        float Mv;
        if (t == 18) {
            Mv = Mn2;                                   // gi == W-2
        } else {
            const int jj = (t == 19) ? (n - 1) : (gi - 2);
            float acc = 0.f, p = 1.f;
            #pragma unroll 4
            for (int d = 0; d <= 12; ++d) {
                const int j = jj - d;                   // always >= 0
                float b = 6.f * (xr[j + 3] - 2.f * xr[j + 2] + xr[j + 1]);
                if (j == n - 1) b -= Mn2;
                acc = fmaf(p, b, acc);
                p *= LAM;
            }
            p = LAM;
            #pragma unroll 4
            for (int d = 1; d <= 12; ++d) {
                const int j = jj + d;
                if (j < n) {
                    float b = 6.f * (xr[j + 3] - 2.f * xr[j + 2] + xr[j + 1]);
                    acc = fmaf(p, b, acc);
                }
                p *= LAM;
            }
            float pw = LAM;                             // lam^{n-jj}
            for (int s = 0; s < n - 1 - jj; ++s) pw *= LAM;
            acc -= pw * SR;
            Mv = ACOEF * acc;
            if (t == 19) Mv = 2.f * Mn2 - Mv;
        }
        sP[gi - kbase + 1] = make_float2(xr[gi], Mv);
    }
    if (kbase + TILE_I == W_DIM && tid == 63)
        sP[SPN - 1] = make_float2(0.f, 0.f);            // ghost knot W (slot 1025)
    __syncthreads();

    // ---- evaluate: static split; per chunk 3 LDS.64 + coef build,
    //      per point 1 ADD + 3 FMA; coalesced STG.128 ----
    {
        float4* out4 = (float4*)outr;
        const float s1 = step;
        const float s2 = step + step;                   // exact
        const float s3 = 3.0f * step;
        #pragma unroll
        for (int k = 0; k < TILE_I / NTHR; ++k) {
            const int cl = tid + k * NTHR;
            const int cg = kbase + cl;
            const float q0f = (float)(4 * cg);          // exact
            const float fi0 = (float)(cg - 1);          // exact
            const float u0 = fmaf(q0f, step, -fi0);     // t of pt 0 on A
            const float ub0 = u0 - 1.0f;                // t of pt 0 on B, exact

            const float2 p0 = sP[cl];                   // knot cg-1
            const float2 p1 = sP[cl + 1];               // knot cg
            const float2 p2 = sP[cl + 2];               // knot cg+1 (ghost @ ends)
            const float y0 = p0.x, m0 = p0.y;
            const float y1 = p1.x, m1 = p1.y;
            const float y2 = p2.x, m2 = p2.y;

            const float Ax = y0;
            const float Ay = fmaf(fmaf(2.f, m0, m1), -(1.f / 6.f), y1 - y0);
            const float Az = 0.5f * m0;
            const float Aw = (m1 - m0) * (1.f / 6.f);
            const float Bx = y1;
            const float By = fmaf(fmaf(2.f, m1, m2), -(1.f / 6.f), y2 - y1);
            const float Bz = 0.5f * m1;
            const float Bw = (m2 - m1) * (1.f / 6.f);

            #define EVA(t) fmaf((t), fmaf((t), fmaf((t), Aw, Az), Ay), Ax)
            #define EVB(t) fmaf((t), fmaf((t), fmaf((t), Bw, Bz), By), Bx)

            const int cg3 = 3 * cg;
            float4 r;
            if (cg3 > 16382) {                          // cg >= 5461
                if (cg == W_DIM - 1) {                  // cg == 8191: A A A A
                    r.x = EVA(u0);      r.y = EVA(u0 + s1);
                    r.z = EVA(u0 + s2); r.w = EVA(u0 + s3);
                } else {                                // A A A B
                    r.x = EVA(u0);      r.y = EVA(u0 + s1);
                    r.z = EVA(u0 + s2); r.w = EVB(ub0 + s3);
                }
            } else if (cg3 > 8191) {                    // cg in [2731,5460]: A A B B
                r.x = EVA(u0);       r.y = EVA(u0 + s1);
                r.z = EVB(ub0 + s2); r.w = EVB(ub0 + s3);
            } else if (cg3 > 0) {                       // cg in [1,2730]: A B B B
                r.x = EVA(u0);       r.y = EVB(ub0 + s1);
                r.z = EVB(ub0 + s2); r.w = EVB(ub0 + s3);
            } else {                                    // cg == 0 (fi0 = -1): B B B B
                r.x = EVB(ub0);      r.y = EVB(ub0 + s1);
                r.z = EVB(ub0 + s2); r.w = EVB(ub0 + s3);
            }
            #undef EVA
            #undef EVB
            out4[cl] = r;
        }
    }
}

extern "C" void kernel_launch(void* const* d_in, const int* in_sizes, int n_in,
                              void* d_out, int out_size) {
    const float* x = (const float*)d_in[0];
    float* out = (float*)d_out;

    const int B = in_sizes[0] / W_DIM;               // 512
    const int nout = out_size / B;                   // 32768
    const float step = (float)((double)(W_DIM - 1) / (double)(nout - 1));

    dim3 grid(W_DIM / TILE_I, B);                    // 8 x 512 = 4096 CTAs
    spline_kernel<<<grid, NTHR>>>(x, out, nout, step);
}